// round 17
// baseline (speedup 1.0000x reference)
#include <cuda_runtime.h>
#include <cuda_bf16.h>
#include <cstdint>

#define VOCAB    50000
#define RQUADS   12500               // vocab row-quads (4 rows each)
#define NSLICES  4
#define QPS      3125                // row-quads per slice (= float4s per slice)
#define GRID     148
#define THREADS  1024
#define PWARPS   30                  // producer warps per block
#define NPW      (GRID * PWARPS)     // 4440 producer warps chip-wide
#define NQUADS   4096                // output cell-quads
#define TABLE_BYTES (VOCAB * 4)      // 200000 B smem

__device__ __align__(16) float g_proj[VOCAB];
__device__ unsigned g_ctr[NSLICES];  // +3125 per replay each (monotonic)
__device__ unsigned g_epoch;         // +148 per replay (monotonic)

// 32-byte L2-evict_last load (sm_103 legal form)
struct f8 { float4 a, b; };
__device__ __forceinline__ f8 ldg_el8(const void* p) {
    unsigned long long x0, x1, x2, x3;
    asm volatile("ld.global.nc.L2::evict_last.v4.b64 {%0,%1,%2,%3}, [%4];"
                 : "=l"(x0), "=l"(x1), "=l"(x2), "=l"(x3) : "l"(p));
    f8 r;
    r.a.x = __uint_as_float((unsigned)(x0));
    r.a.y = __uint_as_float((unsigned)(x0 >> 32));
    r.a.z = __uint_as_float((unsigned)(x1));
    r.a.w = __uint_as_float((unsigned)(x1 >> 32));
    r.b.x = __uint_as_float((unsigned)(x2));
    r.b.y = __uint_as_float((unsigned)(x2 >> 32));
    r.b.z = __uint_as_float((unsigned)(x3));
    r.b.w = __uint_as_float((unsigned)(x3 >> 32));
    return r;
}
__device__ __forceinline__ float dot8(const f8& v, const float4& w0, const float4& w1) {
    float s = 0.f;
    s = fmaf(v.a.x, w0.x, s); s = fmaf(v.a.y, w0.y, s);
    s = fmaf(v.a.z, w0.z, s); s = fmaf(v.a.w, w0.w, s);
    s = fmaf(v.b.x, w1.x, s); s = fmaf(v.b.y, w1.y, s);
    s = fmaf(v.b.z, w1.z, s); s = fmaf(v.b.w, w1.w, s);
    return s;
}

__global__ void __launch_bounds__(THREADS, 1) fused_kernel(
    const int*   __restrict__ x,
    const float* __restrict__ E,
    const float* __restrict__ W,
    const float* __restrict__ bias,
    float*       __restrict__ out)
{
    extern __shared__ float s_proj[];     // 200000 B, slices contiguous
    __shared__ unsigned s_r;              // replay index

    int tid  = threadIdx.x;
    int lane = tid & 31;
    int wid  = tid >> 5;                  // 0..31
    int gw   = blockIdx.x * 32 + wid;     // gather warp id

    if (tid == 0) {
        unsigned old = atomicAdd(&g_epoch, 1u);
        s_r = old / (unsigned)GRID;       // exact replay index (single wave)
    }

    // prefetch x + bias (independent of everything)
    int4 t = make_int4(0, 0, 0, 0);
    if (gw < NQUADS)
        t = reinterpret_cast<const int4*>(x)[gw * 32 + lane];
    float bv = bias[0];

    __syncthreads();
    unsigned r = s_r;

    if (wid < PWARPS) {
        // ================= producers: proj stream =================
        const char* __restrict__ Eb = reinterpret_cast<const char*>(E);
        const float4* __restrict__ w4 = reinterpret_cast<const float4*>(W);
        float4 w0 = w4[lane * 2];
        float4 w1 = w4[lane * 2 + 1];

        int pw = blockIdx.x * PWARPS + wid;   // 0..4439

        #pragma unroll
        for (int it = 0; it < 3; ++it) {
            int q = pw + it * NPW;
            if (q < RQUADS) {
                int row0 = q * 4;
                size_t off = (size_t)row0 * 1024 + lane * 32;
                f8 r0 = ldg_el8(Eb + off);
                f8 r1 = ldg_el8(Eb + off + 1024);
                f8 r2 = ldg_el8(Eb + off + 2048);
                f8 r3 = ldg_el8(Eb + off + 3072);

                float s0 = dot8(r0, w0, w1);
                float s1 = dot8(r1, w0, w1);
                float s2 = dot8(r2, w0, w1);
                float s3 = dot8(r3, w0, w1);

                #pragma unroll
                for (int o = 16; o > 0; o >>= 1) {
                    s0 += __shfl_xor_sync(0xFFFFFFFFu, s0, o);
                    s1 += __shfl_xor_sync(0xFFFFFFFFu, s1, o);
                    s2 += __shfl_xor_sync(0xFFFFFFFFu, s2, o);
                    s3 += __shfl_xor_sync(0xFFFFFFFFu, s3, o);
                }
                if (lane == 0) {
                    reinterpret_cast<float4*>(g_proj)[q] =
                        make_float4(s0, s1, s2, s3);
                    unsigned dummy;
                    asm volatile("atom.add.release.gpu.u32 %0, [%1], %2;"
                                 : "=r"(dummy)
                                 : "l"(&g_ctr[q / QPS]), "r"(1u) : "memory");
                }
            }
        }
    } else {
        // ================= consumers: pipelined slice fills =================
        int first = wid - PWARPS;            // 0 or 1
        uint32_t sbase = (uint32_t)__cvta_generic_to_shared(s_proj);
        const float4* __restrict__ g4 = reinterpret_cast<const float4*>(g_proj);

        for (int s = first; s < NSLICES; s += 2) {
            unsigned target = (r + 1u) * (unsigned)QPS;
            if (lane == 0) {
                unsigned cur;
                for (;;) {
                    asm volatile("ld.acquire.gpu.u32 %0, [%1];"
                                 : "=r"(cur) : "l"(&g_ctr[s]) : "memory");
                    if (cur >= target) break;
                    __nanosleep(64);
                }
            }
            __syncwarp();
            // fill slice s: 3125 float4 -> smem at float4 index s*QPS
            for (int i = lane; i < QPS; i += 32) {
                int idx = s * QPS + i;
                asm volatile("cp.async.cg.shared.global [%0], [%1], 16;"
                             :: "r"(sbase + idx * 16), "l"(g4 + idx));
            }
            asm volatile("cp.async.commit_group;");
        }
        asm volatile("cp.async.wait_group 0;" ::: "memory");
    }

    __syncthreads();

    // ================= gather: one cell-quad per warp =================
    if (gw < NQUADS) {
        float s = s_proj[t.x] + s_proj[t.y] + s_proj[t.z] + s_proj[t.w];
        s += __shfl_xor_sync(0xFFFFFFFFu, s, 4);
        s += __shfl_xor_sync(0xFFFFFFFFu, s, 2);
        s += __shfl_xor_sync(0xFFFFFFFFu, s, 1);
        if ((lane & 7) == 0) out[gw * 4 + (lane >> 3)] = s + bv;
    }
}

extern "C" void kernel_launch(void* const* d_in, const int* in_sizes, int n_in,
                              void* d_out, int out_size)
{
    const int*   x = (const int*)  d_in[0];
    const float* E = (const float*)d_in[1];
    const float* W = (const float*)d_in[2];
    const float* b = (const float*)d_in[3];
    float* out = (float*)d_out;

    static bool attr_done = false;
    if (!attr_done) {
        cudaFuncSetAttribute(fused_kernel,
                             cudaFuncAttributeMaxDynamicSharedMemorySize,
                             TABLE_BYTES);
        attr_done = true;
    }

    fused_kernel<<<GRID, THREADS, TABLE_BYTES>>>(x, E, W, b, out);
}